// round 1
// baseline (speedup 1.0000x reference)
#include <cuda_runtime.h>

#define D1 160
#define D2 192
#define D3 224

static constexpr int NVOX = D1 * D2 * D3;   // 6,881,280

__global__ __launch_bounds__(256) void st_warp3d_kernel(
    const float*  __restrict__ vol,   // [D1,D2,D3,2] (batch 0 of input)
    const float*  __restrict__ trf,   // [D1,D2,D3,3] (batch 0 of input)
    float2*       __restrict__ out)   // [D1,D2,D3] of float2
{
    int idx = blockIdx.x * blockDim.x + threadIdx.x;
    if (idx >= NVOX) return;

    // decompose voxel index (z innermost)
    int z  = idx % D3;
    int t  = idx / D3;
    int y  = t % D2;
    int x  = t / D2;

    // dense shift (coalesced: consecutive threads read consecutive 12B chunks)
    const float* tp = trf + (size_t)idx * 3;
    float sx = __ldg(tp + 0);
    float sy = __ldg(tp + 1);
    float sz = __ldg(tp + 2);

    // absolute sample location, clamped to domain
    float lx = fminf(fmaxf((float)x + sx, 0.0f), (float)(D1 - 1));
    float ly = fminf(fmaxf((float)y + sy, 0.0f), (float)(D2 - 1));
    float lz = fminf(fmaxf((float)z + sz, 0.0f), (float)(D3 - 1));

    float fx = floorf(lx), fy = floorf(ly), fz = floorf(lz);
    int ix0 = (int)fx, iy0 = (int)fy, iz0 = (int)fz;
    int ix1 = min(ix0 + 1, D1 - 1);
    int iy1 = min(iy0 + 1, D2 - 1);
    int iz1 = min(iz0 + 1, D3 - 1);

    float wx1 = lx - fx, wx0 = 1.0f - wx1;
    float wy1 = ly - fy, wy0 = 1.0f - wy1;
    float wz1 = lz - fz, wz0 = 1.0f - wz1;

    // vol viewed as float2 (channel pair contiguous)
    const float2* v = (const float2*)vol;

    int r00 = (ix0 * D2 + iy0) * D3;
    int r01 = (ix0 * D2 + iy1) * D3;
    int r10 = (ix1 * D2 + iy0) * D3;
    int r11 = (ix1 * D2 + iy1) * D3;

    float2 c000 = __ldg(v + r00 + iz0);
    float2 c001 = __ldg(v + r00 + iz1);
    float2 c010 = __ldg(v + r01 + iz0);
    float2 c011 = __ldg(v + r01 + iz1);
    float2 c100 = __ldg(v + r10 + iz0);
    float2 c101 = __ldg(v + r10 + iz1);
    float2 c110 = __ldg(v + r11 + iz0);
    float2 c111 = __ldg(v + r11 + iz1);

    float w000 = wx0 * wy0 * wz0;
    float w001 = wx0 * wy0 * wz1;
    float w010 = wx0 * wy1 * wz0;
    float w011 = wx0 * wy1 * wz1;
    float w100 = wx1 * wy0 * wz0;
    float w101 = wx1 * wy0 * wz1;
    float w110 = wx1 * wy1 * wz0;
    float w111 = wx1 * wy1 * wz1;

    float2 acc;
    acc.x = w000 * c000.x + w001 * c001.x + w010 * c010.x + w011 * c011.x
          + w100 * c100.x + w101 * c101.x + w110 * c110.x + w111 * c111.x;
    acc.y = w000 * c000.y + w001 * c001.y + w010 * c010.y + w011 * c011.y
          + w100 * c100.y + w101 * c101.y + w110 * c110.y + w111 * c111.y;

    out[idx] = acc;
}

extern "C" void kernel_launch(void* const* d_in, const int* in_sizes, int n_in,
                              void* d_out, int out_size)
{
    const float* vol = (const float*)d_in[0];  // [2,160,192,224,2] -> use batch 0
    const float* trf = (const float*)d_in[1];  // [2,160,192,224,3] -> use batch 0
    float2* out = (float2*)d_out;

    int threads = 256;
    int blocks = (NVOX + threads - 1) / threads;
    st_warp3d_kernel<<<blocks, threads>>>(vol, trf, out);
}